// round 4
// baseline (speedup 1.0000x reference)
#include <cuda_runtime.h>

#define NTHR  256
#define BT    32
#define H     128
#define G     512
#define T_SEQ 32
#define B_TOT 32768
#define PL    12
#define P_DROP 0.3f
#define DROP_SCALE (1.0f / 0.7f)

#define AROW  132                 // A row stride (words): 128 + 4 pad
#define ASZ   (BT * AROW + 16)    // + slack for the per-bg +4 offset
#define WSZ   (G * 32)            // 512 rows x 32 k-chunk, xor-swizzled granules

struct Smem {
    float At0[ASZ];     // h0 (and decoder h), [b][k] k-contiguous
    float At1[ASZ];     // h1
    float Dt [ASZ];     // dropped layer0 output
    float Ct0[BT * H];  // c state layer0
    float Ct1[BT * H];  // c state layer1 / decoder
    float W  [WSZ];     // staged weight chunk
    float B0 [G], B1 [G], BC [G];
    float Wih0[G * 2], Wihc[G * 2];
    float Wout[2 * H];
    float bout[2];
    float X  [BT * 2];
};

// ---- packed fp32x2 helpers (exact IEEE fma per lane) ----
__device__ __forceinline__ unsigned long long ffma2(unsigned long long a,
                                                    unsigned long long b,
                                                    unsigned long long c) {
    unsigned long long d;
    asm("fma.rn.f32x2 %0, %1, %2, %3;" : "=l"(d) : "l"(a), "l"(b), "l"(c));
    return d;
}
__device__ __forceinline__ unsigned long long pack2(float lo, float hi) {
    unsigned long long d;
    asm("mov.b64 %0, {%1, %2};" : "=l"(d) : "f"(lo), "f"(hi));
    return d;
}
__device__ __forceinline__ float2 unpack2(unsigned long long v) {
    float2 r;
    asm("mov.b64 {%0, %1}, %2;" : "=f"(r.x), "=f"(r.y) : "l"(v));
    return r;
}
__device__ __forceinline__ float tanh_ap(float x) {
    float y;
    asm("tanh.approx.f32 %0, %1;" : "=f"(y) : "f"(x));
    return y;
}
__device__ __forceinline__ float sig_ap(float x) {
    return fmaf(tanh_ap(0.5f * x), 0.5f, 0.5f);
}

// A addressing: [b][k], row stride AROW, +4-word shift per batch-group of 8
// -> the 4 distinct lanes of an LDS.128 phase land on distinct granules.
__device__ __forceinline__ int aidx(int b, int k) {
    return b * AROW + ((b >> 3) << 2) + k;
}

// acc[g][ui][bi] over k-pairs.  C[32b x 512j] += A[32 x 128] * W[512 x 128]^T
__device__ __forceinline__ void gemm_step(const float* __restrict__ Wg,
                                          const float* __restrict__ A,
                                          float* __restrict__ sW,
                                          unsigned long long acc[4][2][8],
                                          int tid, int bg, int ug)
{
    const int ugx = ug & 7;
    const float* abase = A + bg * 8 * AROW + bg * 4;
    const int jstage = tid >> 3;
    const int gkstage = tid & 7;

#pragma unroll 1
    for (int ch = 0; ch < 4; ++ch) {
        __syncthreads();
        {
            const float4* src = (const float4*)(Wg + ch * 32 + gkstage * 4);
#pragma unroll
            for (int it = 0; it < 16; ++it) {
                int j = jstage + it * 32;
                float4 v = src[j * 32];            // Wg + j*128 + ch*32 + gk*4
                int gran = gkstage ^ ((j >> 1) & 7);
                *(float4*)(sW + j * 32 + gran * 4) = v;
            }
        }
        __syncthreads();

        const float* ab = abase + ch * 32;
#pragma unroll
        for (int k4 = 0; k4 < 8; ++k4) {
            const int gran = (k4 ^ ugx) << 2;
            unsigned long long w0[4][2], w1[4][2];
#pragma unroll
            for (int g = 0; g < 4; ++g)
#pragma unroll
                for (int ui = 0; ui < 2; ++ui) {
                    int j = g * H + ug * 2 + ui;
                    ulonglong2 wv = *(const ulonglong2*)(sW + j * 32 + gran);
                    w0[g][ui] = wv.x;
                    w1[g][ui] = wv.y;
                }
#pragma unroll
            for (int bi = 0; bi < 8; ++bi) {
                ulonglong2 av = *(const ulonglong2*)(ab + bi * AROW + k4 * 4);
#pragma unroll
                for (int g = 0; g < 4; ++g)
#pragma unroll
                    for (int ui = 0; ui < 2; ++ui) {
                        acc[g][ui][bi] = ffma2(w0[g][ui], av.x, acc[g][ui][bi]);
                        acc[g][ui][bi] = ffma2(w1[g][ui], av.y, acc[g][ui][bi]);
                    }
            }
        }
    }
}

__global__ void __launch_bounds__(NTHR, 1)
mcdrop_lstm_kernel(const float* __restrict__ obs,
                   const float* __restrict__ Wih0, const float* __restrict__ Whh0,
                   const float* __restrict__ bih0, const float* __restrict__ bhh0,
                   const float* __restrict__ Wih1, const float* __restrict__ Whh1,
                   const float* __restrict__ bih1, const float* __restrict__ bhh1,
                   const float* __restrict__ Wihc, const float* __restrict__ Whhc,
                   const float* __restrict__ bihc, const float* __restrict__ bhhc,
                   const float* __restrict__ Wout, const float* __restrict__ bout,
                   const float* __restrict__ encu, const float* __restrict__ hnu,
                   const float* __restrict__ decu, float* __restrict__ preds)
{
    extern __shared__ float smraw[];
    Smem* S = (Smem*)smraw;

    const int tid = threadIdx.x;
    const int bg  = tid & 3;      // 4 batch groups of 8
    const int ug  = tid >> 2;     // 64 unit groups of 2
    const int bglob0 = blockIdx.x * BT;

    for (int i = tid; i < G; i += NTHR) {
        S->B0[i] = bih0[i] + bhh0[i];
        S->B1[i] = bih1[i] + bhh1[i];
        S->BC[i] = bihc[i] + bhhc[i];
        S->Wih0[i * 2]     = Wih0[i * 2];
        S->Wih0[i * 2 + 1] = Wih0[i * 2 + 1];
        S->Wihc[i * 2]     = Wihc[i * 2];
        S->Wihc[i * 2 + 1] = Wihc[i * 2 + 1];
    }
    for (int i = tid; i < 2 * H; i += NTHR) S->Wout[i] = Wout[i];
    if (tid < 2) S->bout[tid] = bout[tid];
    for (int i = tid; i < ASZ; i += NTHR) {
        S->At0[i] = 0.0f; S->At1[i] = 0.0f; S->Dt[i] = 0.0f;
    }
    for (int i = tid; i < BT * H; i += NTHR) {
        S->Ct0[i] = 0.0f; S->Ct1[i] = 0.0f;
    }

    unsigned long long acc[4][2][8];

    // ===================== encoder =====================
#pragma unroll 1
    for (int t = 0; t < T_SEQ; ++t) {
        // ---- layer 0: acc = b0 + x_t @ Wih0^T (into lo lane) ----
        float2 xv[8];
#pragma unroll
        for (int bi = 0; bi < 8; ++bi)
            xv[bi] = *(const float2*)(obs + (size_t)(bglob0 + bg * 8 + bi) * (T_SEQ * 2) + t * 2);
#pragma unroll
        for (int g = 0; g < 4; ++g)
#pragma unroll
            for (int ui = 0; ui < 2; ++ui) {
                int j = g * H + ug * 2 + ui;
                float bb  = S->B0[j];
                float wi0 = S->Wih0[j * 2];
                float wi1 = S->Wih0[j * 2 + 1];
#pragma unroll
                for (int bi = 0; bi < 8; ++bi) {
                    float lo = fmaf(wi1, xv[bi].y, fmaf(wi0, xv[bi].x, bb));
                    acc[g][ui][bi] = pack2(lo, 0.0f);
                }
            }
        gemm_step(Whh0, S->At0, S->W, acc, tid, bg, ug);
        __syncthreads();   // everyone done reading At0 before we overwrite it

#pragma unroll
        for (int bi = 0; bi < 8; ++bi) {
            int b = bg * 8 + bi;
            int bgl = bglob0 + b;
            float2 uu = *(const float2*)(encu + ((size_t)t * B_TOT + bgl) * H + ug * 2);
#pragma unroll
            for (int ui = 0; ui < 2; ++ui) {
                int u = ug * 2 + ui;
                float2 pi = unpack2(acc[0][ui][bi]);
                float2 pf = unpack2(acc[1][ui][bi]);
                float2 pg = unpack2(acc[2][ui][bi]);
                float2 po = unpack2(acc[3][ui][bi]);
                float iv = sig_ap(pi.x + pi.y);
                float fv = sig_ap(pf.x + pf.y);
                float gv = tanh_ap(pg.x + pg.y);
                float ov = sig_ap(po.x + po.y);
                float c  = fmaf(fv, S->Ct0[b * H + u], iv * gv);
                S->Ct0[b * H + u] = c;
                float h  = ov * tanh_ap(c);
                float um = (ui == 0) ? uu.x : uu.y;
                S->At0[aidx(b, u)] = h;
                S->Dt [aidx(b, u)] = (um >= P_DROP) ? h * DROP_SCALE : 0.0f;
            }
        }

        // ---- layer 1 ----
#pragma unroll
        for (int g = 0; g < 4; ++g)
#pragma unroll
            for (int ui = 0; ui < 2; ++ui) {
                float bb = S->B1[g * H + ug * 2 + ui];
#pragma unroll
                for (int bi = 0; bi < 8; ++bi)
                    acc[g][ui][bi] = pack2(bb, 0.0f);
            }
        gemm_step(Wih1, S->Dt,  S->W, acc, tid, bg, ug);
        gemm_step(Whh1, S->At1, S->W, acc, tid, bg, ug);
        __syncthreads();

#pragma unroll
        for (int bi = 0; bi < 8; ++bi) {
            int b = bg * 8 + bi;
#pragma unroll
            for (int ui = 0; ui < 2; ++ui) {
                int u = ug * 2 + ui;
                float2 pi = unpack2(acc[0][ui][bi]);
                float2 pf = unpack2(acc[1][ui][bi]);
                float2 pg = unpack2(acc[2][ui][bi]);
                float2 po = unpack2(acc[3][ui][bi]);
                float iv = sig_ap(pi.x + pi.y);
                float fv = sig_ap(pf.x + pf.y);
                float gv = tanh_ap(pg.x + pg.y);
                float ov = sig_ap(po.x + po.y);
                float c  = fmaf(fv, S->Ct1[b * H + u], iv * gv);
                S->Ct1[b * H + u] = c;
                S->At1[aidx(b, u)] = ov * tanh_ap(c);
            }
        }
    }

    // ===================== decoder init =====================
#pragma unroll
    for (int bi = 0; bi < 8; ++bi) {
        int b = bg * 8 + bi;
        int bgl = bglob0 + b;
        float2 uu = *(const float2*)(hnu + (size_t)bgl * H + ug * 2);
#pragma unroll
        for (int ui = 0; ui < 2; ++ui) {
            int u = ug * 2 + ui;
            float h1v = S->At1[aidx(b, u)];   // own writes
            float um = (ui == 0) ? uu.x : uu.y;
            S->At0[aidx(b, u)] = (um >= P_DROP) ? h1v * DROP_SCALE : 0.0f;
        }
    }
    if (tid < BT * 2) {
        int b = tid >> 1, d = tid & 1;
        S->X[tid] = obs[(size_t)(bglob0 + b) * (T_SEQ * 2) + (size_t)(T_SEQ - 1) * 2 + d];
    }

    // ===================== decoder =====================
#pragma unroll 1
    for (int p = 0; p < PL; ++p) {
        __syncthreads();
        float2 xi[8];
#pragma unroll
        for (int bi = 0; bi < 8; ++bi)
            xi[bi] = *(const float2*)(&S->X[(bg * 8 + bi) * 2]);
#pragma unroll
        for (int g = 0; g < 4; ++g)
#pragma unroll
            for (int ui = 0; ui < 2; ++ui) {
                int j = g * H + ug * 2 + ui;
                float bb  = S->BC[j];
                float wi0 = S->Wihc[j * 2];
                float wi1 = S->Wihc[j * 2 + 1];
#pragma unroll
                for (int bi = 0; bi < 8; ++bi) {
                    float lo = fmaf(wi1, xi[bi].y, fmaf(wi0, xi[bi].x, bb));
                    acc[g][ui][bi] = pack2(lo, 0.0f);
                }
            }
        gemm_step(Whhc, S->At0, S->W, acc, tid, bg, ug);
        __syncthreads();

#pragma unroll
        for (int bi = 0; bi < 8; ++bi) {
            int b = bg * 8 + bi;
            int bgl = bglob0 + b;
            float2 uu = *(const float2*)(decu + ((size_t)p * B_TOT + bgl) * H + ug * 2);
#pragma unroll
            for (int ui = 0; ui < 2; ++ui) {
                int u = ug * 2 + ui;
                float2 pi = unpack2(acc[0][ui][bi]);
                float2 pf = unpack2(acc[1][ui][bi]);
                float2 pg = unpack2(acc[2][ui][bi]);
                float2 po = unpack2(acc[3][ui][bi]);
                float iv = sig_ap(pi.x + pi.y);
                float fv = sig_ap(pf.x + pf.y);
                float gv = tanh_ap(pg.x + pg.y);
                float ov = sig_ap(po.x + po.y);
                float c  = fmaf(fv, S->Ct1[b * H + u], iv * gv);
                S->Ct1[b * H + u] = c;
                float h  = ov * tanh_ap(c);
                float um = (ui == 0) ? uu.x : uu.y;
                S->At0[aidx(b, u)] = (um >= P_DROP) ? h * DROP_SCALE : 0.0f;
            }
        }
        __syncthreads();

        if (tid < BT * 2) {
            int b = tid >> 1, d = tid & 1;
            float s = S->bout[d];
            const float* wr = &S->Wout[d * H];
#pragma unroll 8
            for (int k = 0; k < H; ++k)
                s = fmaf(wr[k], S->At0[aidx(b, k)], s);
            S->X[b * 2 + d] = s;
            preds[((size_t)(bglob0 + b) * PL + p) * 2 + d] = s;
        }
    }
}

extern "C" void kernel_launch(void* const* d_in, const int* in_sizes, int n_in,
                              void* d_out, int out_size) {
    (void)in_sizes; (void)n_in; (void)out_size;
    const float* obs  = (const float*)d_in[0];
    const float* Wih0 = (const float*)d_in[1];
    const float* Whh0 = (const float*)d_in[2];
    const float* bih0 = (const float*)d_in[3];
    const float* bhh0 = (const float*)d_in[4];
    const float* Wih1 = (const float*)d_in[5];
    const float* Whh1 = (const float*)d_in[6];
    const float* bih1 = (const float*)d_in[7];
    const float* bhh1 = (const float*)d_in[8];
    const float* Wihc = (const float*)d_in[9];
    const float* Whhc = (const float*)d_in[10];
    const float* bihc = (const float*)d_in[11];
    const float* bhhc = (const float*)d_in[12];
    const float* Wout = (const float*)d_in[13];
    const float* bout = (const float*)d_in[14];
    const float* encu = (const float*)d_in[15];
    const float* hnu  = (const float*)d_in[16];
    const float* decu = (const float*)d_in[17];
    float* preds = (float*)d_out;

    int smem = (int)sizeof(Smem);
    cudaFuncSetAttribute(mcdrop_lstm_kernel,
                         cudaFuncAttributeMaxDynamicSharedMemorySize, smem);
    mcdrop_lstm_kernel<<<B_TOT / BT, NTHR, smem>>>(
        obs, Wih0, Whh0, bih0, bhh0, Wih1, Whh1, bih1, bhh1,
        Wihc, Whhc, bihc, bhhc, Wout, bout, encu, hnu, decu, preds);
}

// round 5
// speedup vs baseline: 1.0575x; 1.0575x over previous
#include <cuda_runtime.h>

#define NTHR  256
#define BT    32
#define H     128
#define G     512
#define T_SEQ 32
#define B_TOT 32768
#define PL    12
#define P_DROP 0.3f
#define DROP_SCALE (1.0f / 0.7f)

#define AROW  132                 // A row stride (words): 128 + 4 pad
#define ASZ   (BT * AROW + 16)    // + slack for the per-bg +4 offset
#define WSZ   (G * 32)            // 512 rows x 32 k-chunk, xor-swizzled granules

struct Smem {
    float At0[ASZ];     // h0 (and decoder h), [b][k] k-contiguous
    float At1[ASZ];     // h1
    float Dt [ASZ];     // dropped layer0 output
    float Ct0[BT * H];  // c state layer0
    float Ct1[BT * H];  // c state layer1 / decoder
    float W  [WSZ];     // staged weight chunk
    float B0 [G], B1 [G], BC [G];
    float Wih0[G * 2], Wihc[G * 2];
    float Wout[2 * H];
    float bout[2];
    float X  [BT * 2];
};

// ---- packed fp32x2 helpers (exact IEEE fma per lane) ----
__device__ __forceinline__ unsigned long long ffma2(unsigned long long a,
                                                    unsigned long long b,
                                                    unsigned long long c) {
    unsigned long long d;
    asm("fma.rn.f32x2 %0, %1, %2, %3;" : "=l"(d) : "l"(a), "l"(b), "l"(c));
    return d;
}
__device__ __forceinline__ unsigned long long pack2(float lo, float hi) {
    unsigned long long d;
    asm("mov.b64 %0, {%1, %2};" : "=l"(d) : "f"(lo), "f"(hi));
    return d;
}
__device__ __forceinline__ float2 unpack2(unsigned long long v) {
    float2 r;
    asm("mov.b64 {%0, %1}, %2;" : "=f"(r.x), "=f"(r.y) : "l"(v));
    return r;
}
__device__ __forceinline__ float tanh_ap(float x) {
    float y;
    asm("tanh.approx.f32 %0, %1;" : "=f"(y) : "f"(x));
    return y;
}
__device__ __forceinline__ float sig_ap(float x) {
    return fmaf(tanh_ap(0.5f * x), 0.5f, 0.5f);
}

// A addressing: [b][k], row stride AROW, +4-word shift per batch-group of 8
// -> the 4 distinct lanes of an LDS.128 phase land on distinct granules.
__device__ __forceinline__ int aidx(int b, int k) {
    return b * AROW + ((b >> 3) << 2) + k;
}

// acc[g][ui][bi] over k-pairs.  C[32b x 512j] += A[32 x 128] * W[512 x 128]^T
__device__ __forceinline__ void gemm_step(const float* __restrict__ Wg,
                                          const float* __restrict__ A,
                                          float* __restrict__ sW,
                                          unsigned long long acc[4][2][8],
                                          int tid, int bg, int ug)
{
    const int ugx = ug & 7;
    const float* abase = A + bg * 8 * AROW + bg * 4;
    const int jstage = tid >> 3;
    const int gkstage = tid & 7;

#pragma unroll 1
    for (int ch = 0; ch < 4; ++ch) {
        __syncthreads();
        {
            const float4* src = (const float4*)(Wg + ch * 32 + gkstage * 4);
#pragma unroll
            for (int it = 0; it < 16; ++it) {
                int j = jstage + it * 32;
                float4 v = src[j * 32];            // Wg + j*128 + ch*32 + gk*4
                int gran = gkstage ^ ((j >> 1) & 7);
                *(float4*)(sW + j * 32 + gran * 4) = v;
            }
        }
        __syncthreads();

        const float* ab = abase + ch * 32;
#pragma unroll
        for (int k4 = 0; k4 < 8; ++k4) {
            const int gran = (k4 ^ ugx) << 2;
            unsigned long long w0[4][2], w1[4][2];
#pragma unroll
            for (int g = 0; g < 4; ++g)
#pragma unroll
                for (int ui = 0; ui < 2; ++ui) {
                    int j = g * H + ug * 2 + ui;
                    ulonglong2 wv = *(const ulonglong2*)(sW + j * 32 + gran);
                    w0[g][ui] = wv.x;
                    w1[g][ui] = wv.y;
                }
#pragma unroll
            for (int bi = 0; bi < 8; ++bi) {
                ulonglong2 av = *(const ulonglong2*)(ab + bi * AROW + k4 * 4);
#pragma unroll
                for (int g = 0; g < 4; ++g)
#pragma unroll
                    for (int ui = 0; ui < 2; ++ui) {
                        acc[g][ui][bi] = ffma2(w0[g][ui], av.x, acc[g][ui][bi]);
                        acc[g][ui][bi] = ffma2(w1[g][ui], av.y, acc[g][ui][bi]);
                    }
            }
        }
    }
}

__global__ void __launch_bounds__(NTHR, 1)
mcdrop_lstm_kernel(const float* __restrict__ obs,
                   const float* __restrict__ Wih0, const float* __restrict__ Whh0,
                   const float* __restrict__ bih0, const float* __restrict__ bhh0,
                   const float* __restrict__ Wih1, const float* __restrict__ Whh1,
                   const float* __restrict__ bih1, const float* __restrict__ bhh1,
                   const float* __restrict__ Wihc, const float* __restrict__ Whhc,
                   const float* __restrict__ bihc, const float* __restrict__ bhhc,
                   const float* __restrict__ Wout, const float* __restrict__ bout,
                   const float* __restrict__ encu, const float* __restrict__ hnu,
                   const float* __restrict__ decu, float* __restrict__ preds)
{
    extern __shared__ float smraw[];
    Smem* S = (Smem*)smraw;

    const int tid = threadIdx.x;
    const int bg  = tid & 3;      // 4 batch groups of 8
    const int ug  = tid >> 2;     // 64 unit groups of 2
    const int bglob0 = blockIdx.x * BT;

    for (int i = tid; i < G; i += NTHR) {
        S->B0[i] = bih0[i] + bhh0[i];
        S->B1[i] = bih1[i] + bhh1[i];
        S->BC[i] = bihc[i] + bhhc[i];
        S->Wih0[i * 2]     = Wih0[i * 2];
        S->Wih0[i * 2 + 1] = Wih0[i * 2 + 1];
        S->Wihc[i * 2]     = Wihc[i * 2];
        S->Wihc[i * 2 + 1] = Wihc[i * 2 + 1];
    }
    for (int i = tid; i < 2 * H; i += NTHR) S->Wout[i] = Wout[i];
    if (tid < 2) S->bout[tid] = bout[tid];
    for (int i = tid; i < ASZ; i += NTHR) {
        S->At0[i] = 0.0f; S->At1[i] = 0.0f; S->Dt[i] = 0.0f;
    }
    for (int i = tid; i < BT * H; i += NTHR) {
        S->Ct0[i] = 0.0f; S->Ct1[i] = 0.0f;
    }

    unsigned long long acc[4][2][8];

    // ===================== encoder =====================
#pragma unroll 1
    for (int t = 0; t < T_SEQ; ++t) {
        // ---- layer 0: acc = b0 + x_t @ Wih0^T (into lo lane) ----
        float2 xv[8];
#pragma unroll
        for (int bi = 0; bi < 8; ++bi)
            xv[bi] = *(const float2*)(obs + (size_t)(bglob0 + bg * 8 + bi) * (T_SEQ * 2) + t * 2);
#pragma unroll
        for (int g = 0; g < 4; ++g)
#pragma unroll
            for (int ui = 0; ui < 2; ++ui) {
                int j = g * H + ug * 2 + ui;
                float bb  = S->B0[j];
                float wi0 = S->Wih0[j * 2];
                float wi1 = S->Wih0[j * 2 + 1];
#pragma unroll
                for (int bi = 0; bi < 8; ++bi) {
                    float lo = fmaf(wi1, xv[bi].y, fmaf(wi0, xv[bi].x, bb));
                    acc[g][ui][bi] = pack2(lo, 0.0f);
                }
            }
        gemm_step(Whh0, S->At0, S->W, acc, tid, bg, ug);
        __syncthreads();   // everyone done reading At0 before we overwrite it

#pragma unroll
        for (int bi = 0; bi < 8; ++bi) {
            int b = bg * 8 + bi;
            int bgl = bglob0 + b;
            float2 uu = *(const float2*)(encu + ((size_t)t * B_TOT + bgl) * H + ug * 2);
#pragma unroll
            for (int ui = 0; ui < 2; ++ui) {
                int u = ug * 2 + ui;
                float2 pi = unpack2(acc[0][ui][bi]);
                float2 pf = unpack2(acc[1][ui][bi]);
                float2 pg = unpack2(acc[2][ui][bi]);
                float2 po = unpack2(acc[3][ui][bi]);
                float iv = sig_ap(pi.x + pi.y);
                float fv = sig_ap(pf.x + pf.y);
                float gv = tanh_ap(pg.x + pg.y);
                float ov = sig_ap(po.x + po.y);
                float c  = fmaf(fv, S->Ct0[b * H + u], iv * gv);
                S->Ct0[b * H + u] = c;
                float h  = ov * tanh_ap(c);
                float um = (ui == 0) ? uu.x : uu.y;
                S->At0[aidx(b, u)] = h;
                S->Dt [aidx(b, u)] = (um >= P_DROP) ? h * DROP_SCALE : 0.0f;
            }
        }

        // ---- layer 1 ----
#pragma unroll
        for (int g = 0; g < 4; ++g)
#pragma unroll
            for (int ui = 0; ui < 2; ++ui) {
                float bb = S->B1[g * H + ug * 2 + ui];
#pragma unroll
                for (int bi = 0; bi < 8; ++bi)
                    acc[g][ui][bi] = pack2(bb, 0.0f);
            }
        gemm_step(Wih1, S->Dt,  S->W, acc, tid, bg, ug);
        gemm_step(Whh1, S->At1, S->W, acc, tid, bg, ug);
        __syncthreads();

#pragma unroll
        for (int bi = 0; bi < 8; ++bi) {
            int b = bg * 8 + bi;
#pragma unroll
            for (int ui = 0; ui < 2; ++ui) {
                int u = ug * 2 + ui;
                float2 pi = unpack2(acc[0][ui][bi]);
                float2 pf = unpack2(acc[1][ui][bi]);
                float2 pg = unpack2(acc[2][ui][bi]);
                float2 po = unpack2(acc[3][ui][bi]);
                float iv = sig_ap(pi.x + pi.y);
                float fv = sig_ap(pf.x + pf.y);
                float gv = tanh_ap(pg.x + pg.y);
                float ov = sig_ap(po.x + po.y);
                float c  = fmaf(fv, S->Ct1[b * H + u], iv * gv);
                S->Ct1[b * H + u] = c;
                S->At1[aidx(b, u)] = ov * tanh_ap(c);
            }
        }
    }

    // ===================== decoder init =====================
#pragma unroll
    for (int bi = 0; bi < 8; ++bi) {
        int b = bg * 8 + bi;
        int bgl = bglob0 + b;
        float2 uu = *(const float2*)(hnu + (size_t)bgl * H + ug * 2);
#pragma unroll
        for (int ui = 0; ui < 2; ++ui) {
            int u = ug * 2 + ui;
            float h1v = S->At1[aidx(b, u)];   // own writes
            float um = (ui == 0) ? uu.x : uu.y;
            S->At0[aidx(b, u)] = (um >= P_DROP) ? h1v * DROP_SCALE : 0.0f;
        }
    }
    if (tid < BT * 2) {
        int b = tid >> 1, d = tid & 1;
        S->X[tid] = obs[(size_t)(bglob0 + b) * (T_SEQ * 2) + (size_t)(T_SEQ - 1) * 2 + d];
    }

    // ===================== decoder =====================
#pragma unroll 1
    for (int p = 0; p < PL; ++p) {
        __syncthreads();
        float2 xi[8];
#pragma unroll
        for (int bi = 0; bi < 8; ++bi)
            xi[bi] = *(const float2*)(&S->X[(bg * 8 + bi) * 2]);
#pragma unroll
        for (int g = 0; g < 4; ++g)
#pragma unroll
            for (int ui = 0; ui < 2; ++ui) {
                int j = g * H + ug * 2 + ui;
                float bb  = S->BC[j];
                float wi0 = S->Wihc[j * 2];
                float wi1 = S->Wihc[j * 2 + 1];
#pragma unroll
                for (int bi = 0; bi < 8; ++bi) {
                    float lo = fmaf(wi1, xi[bi].y, fmaf(wi0, xi[bi].x, bb));
                    acc[g][ui][bi] = pack2(lo, 0.0f);
                }
            }
        gemm_step(Whhc, S->At0, S->W, acc, tid, bg, ug);
        __syncthreads();

#pragma unroll
        for (int bi = 0; bi < 8; ++bi) {
            int b = bg * 8 + bi;
            int bgl = bglob0 + b;
            float2 uu = *(const float2*)(decu + ((size_t)p * B_TOT + bgl) * H + ug * 2);
#pragma unroll
            for (int ui = 0; ui < 2; ++ui) {
                int u = ug * 2 + ui;
                float2 pi = unpack2(acc[0][ui][bi]);
                float2 pf = unpack2(acc[1][ui][bi]);
                float2 pg = unpack2(acc[2][ui][bi]);
                float2 po = unpack2(acc[3][ui][bi]);
                float iv = sig_ap(pi.x + pi.y);
                float fv = sig_ap(pf.x + pf.y);
                float gv = tanh_ap(pg.x + pg.y);
                float ov = sig_ap(po.x + po.y);
                float c  = fmaf(fv, S->Ct1[b * H + u], iv * gv);
                S->Ct1[b * H + u] = c;
                float h  = ov * tanh_ap(c);
                float um = (ui == 0) ? uu.x : uu.y;
                S->At0[aidx(b, u)] = (um >= P_DROP) ? h * DROP_SCALE : 0.0f;
            }
        }
        __syncthreads();

        if (tid < BT * 2) {
            int b = tid >> 1, d = tid & 1;
            float s = S->bout[d];
            const float* wr = &S->Wout[d * H];
#pragma unroll 8
            for (int k = 0; k < H; ++k)
                s = fmaf(wr[k], S->At0[aidx(b, k)], s);
            S->X[b * 2 + d] = s;
            preds[((size_t)(bglob0 + b) * PL + p) * 2 + d] = s;
        }
    }
}

extern "C" void kernel_launch(void* const* d_in, const int* in_sizes, int n_in,
                              void* d_out, int out_size) {
    (void)in_sizes; (void)n_in; (void)out_size;
    const float* obs  = (const float*)d_in[0];
    const float* Wih0 = (const float*)d_in[1];
    const float* Whh0 = (const float*)d_in[2];
    const float* bih0 = (const float*)d_in[3];
    const float* bhh0 = (const float*)d_in[4];
    const float* Wih1 = (const float*)d_in[5];
    const float* Whh1 = (const float*)d_in[6];
    const float* bih1 = (const float*)d_in[7];
    const float* bhh1 = (const float*)d_in[8];
    const float* Wihc = (const float*)d_in[9];
    const float* Whhc = (const float*)d_in[10];
    const float* bihc = (const float*)d_in[11];
    const float* bhhc = (const float*)d_in[12];
    const float* Wout = (const float*)d_in[13];
    const float* bout = (const float*)d_in[14];
    const float* encu = (const float*)d_in[15];
    const float* hnu  = (const float*)d_in[16];
    const float* decu = (const float*)d_in[17];
    float* preds = (float*)d_out;

    int smem = (int)sizeof(Smem);
    cudaFuncSetAttribute(mcdrop_lstm_kernel,
                         cudaFuncAttributeMaxDynamicSharedMemorySize, smem);
    mcdrop_lstm_kernel<<<B_TOT / BT, NTHR, smem>>>(
        obs, Wih0, Whh0, bih0, bhh0, Wih1, Whh1, bih1, bhh1,
        Wihc, Whhc, bihc, bhhc, Wout, bout, encu, hnu, decu, preds);
}